// round 6
// baseline (speedup 1.0000x reference)
#include <cuda_runtime.h>
#include <cstdint>

// AttentionalPropagation, R5: two-kernel tf32 mma.sync design.
// x [B=64, C=512, L=4096] fp32. Per l: q = x[:,:,l]; S = q q^T / sqrt(C);
// P = softmax(S); out = x + P q.
//
// K1: P = softmax(q q^T / sqrt(C)); P stored to __device__ scratch in
//     mma-A-fragment layout (coalesced float4 per lane).
// K2: out = x + P q, with the x residual pre-loaded into the mma accumulator.
//
// Both: NT=1024 (32 warps, 50% occ), 4 warps per l, 8 l per CTA, ~60 regs.
// Staging: LDG.128 -> scalar STS into [l][b][c] pitch-37 smem (STS and
// epilogue conflict-free; fragment LDS <=2-way by construction).

namespace {

constexpr int kB  = 64;
constexpr int kC  = 512;
constexpr int kL  = 4096;
constexpr int LT  = 8;                 // l per CTA (32B global sectors)
constexpr int CCH = 32;                // c per chunk
constexpr int NCH = kC / CCH;          // 16
constexpr int NT  = 1024;              // 32 warps = 4 per l

constexpr int PR    = 37;              // words per b-row (32 data + 5 pad)
constexpr int PLANE = kB * PR;         // 2368 words per l-plane
constexpr int BUF   = LT * PLANE;      // 18944 words per chunk buffer
constexpr int SMEM_BYTES = 2 * BUF * 4;  // 151552 B (both kernels)

// P scratch: [l][strip(4)][s(8)][lane(32)][4] fragment layout, 64 MB.
__device__ float Pg[(size_t)kL * 4 * 8 * 32 * 4];

__device__ __forceinline__ uint32_t fbits(float f) { return __float_as_uint(f); }

__device__ __forceinline__ void mma_tf32(float d[4],
                                         uint32_t a0, uint32_t a1, uint32_t a2, uint32_t a3,
                                         uint32_t b0, uint32_t b1) {
    asm volatile(
        "mma.sync.aligned.m16n8k8.row.col.f32.tf32.tf32.f32 "
        "{%0,%1,%2,%3}, {%4,%5,%6,%7}, {%8,%9}, {%0,%1,%2,%3};"
        : "+f"(d[0]), "+f"(d[1]), "+f"(d[2]), "+f"(d[3])
        : "r"(a0), "r"(a1), "r"(a2), "r"(a3), "r"(b0), "r"(b1));
}

// Each thread owns (b = t&63, c = t>>6) and (b, c+16) of every chunk.
__device__ __forceinline__ void ldg_chunk(const float* __restrict__ x, float4 v[2][2],
                                          int c0, int l0, int sb, int sc) {
    #pragma unroll
    for (int k = 0; k < 2; k++) {
        const float* gp = x + ((size_t)(sb * kC + c0 + sc + 16 * k)) * kL + l0;
        v[k][0] = *(const float4*)gp;
        v[k][1] = *(const float4*)(gp + 4);
    }
}
__device__ __forceinline__ void sts_chunk(float* buf, const float4 v[2][2],
                                          int sb, int sc) {
    #pragma unroll
    for (int k = 0; k < 2; k++) {
        float* p = buf + sb * PR + sc + 16 * k;
        p[0 * PLANE] = v[k][0].x; p[1 * PLANE] = v[k][0].y;
        p[2 * PLANE] = v[k][0].z; p[3 * PLANE] = v[k][0].w;
        p[4 * PLANE] = v[k][1].x; p[5 * PLANE] = v[k][1].y;
        p[6 * PLANE] = v[k][1].z; p[7 * PLANE] = v[k][1].w;
    }
}

// ============================ K1: P = softmax(qq^T/sqrt(C)) =================
__global__ void __launch_bounds__(NT, 1)
k1_scores(const float* __restrict__ x) {
    extern __shared__ float sm[];
    const int t = threadIdx.x, lane = t & 31, w = t >> 5;
    const int l = w >> 2, strip = w & 3;
    const int l0 = blockIdx.x * LT;
    const int r0 = lane >> 2, q4 = lane & 3;
    const int sb = t & 63, sc = t >> 6;

    float acc[8][4];
    #pragma unroll
    for (int j = 0; j < 8; j++)
        #pragma unroll
        for (int i = 0; i < 4; i++) acc[j][i] = 0.0f;

    float4 v[2][2];
    ldg_chunk(x, v, 0, l0, sb, sc);
    sts_chunk(sm, v, sb, sc);
    __syncthreads();

    #pragma unroll 1
    for (int ch = 0; ch < NCH; ch++) {
        if (ch + 1 < NCH) ldg_chunk(x, v, (ch + 1) * CCH, l0, sb, sc);
        const float* pl = sm + (ch & 1) * BUF + l * PLANE;
        #pragma unroll
        for (int s = 0; s < 4; s++) {
            const int ca = 8 * s + q4;
            const float* ap = pl + (strip * 16 + r0) * PR + ca;
            const uint32_t a0 = fbits(ap[0]);
            const uint32_t a1 = fbits(ap[8 * PR]);
            const uint32_t a2 = fbits(ap[4]);
            const uint32_t a3 = fbits(ap[8 * PR + 4]);
            #pragma unroll
            for (int j = 0; j < 8; j++) {
                const float* bp = pl + (8 * j + r0) * PR + ca;
                mma_tf32(acc[j], a0, a1, a2, a3, fbits(bp[0]), fbits(bp[4]));
            }
        }
        if (ch + 1 < NCH) sts_chunk(sm + ((ch + 1) & 1) * BUF, v, sb, sc);
        __syncthreads();
    }

    // Softmax: thread holds rows (strip*16+r0) in acc[j][0..1], (+8) in [2..3];
    // cols 8j+2q4+{0,1} -> row reductions over the q4 quad (xor 1,2).
    {
        const float isc = 0.044194173824159216f;   // 1/sqrt(512)
        #pragma unroll
        for (int h = 0; h < 2; h++) {
            float mx = -1e30f;
            #pragma unroll
            for (int j = 0; j < 8; j++) {
                acc[j][2 * h]     *= isc;
                acc[j][2 * h + 1] *= isc;
                mx = fmaxf(mx, fmaxf(acc[j][2 * h], acc[j][2 * h + 1]));
            }
            mx = fmaxf(mx, __shfl_xor_sync(0xffffffffu, mx, 1));
            mx = fmaxf(mx, __shfl_xor_sync(0xffffffffu, mx, 2));
            float ssum = 0.0f;
            #pragma unroll
            for (int j = 0; j < 8; j++) {
                const float e0 = __expf(acc[j][2 * h] - mx);
                const float e1 = __expf(acc[j][2 * h + 1] - mx);
                acc[j][2 * h] = e0; acc[j][2 * h + 1] = e1;
                ssum += e0 + e1;
            }
            ssum += __shfl_xor_sync(0xffffffffu, ssum, 1);
            ssum += __shfl_xor_sync(0xffffffffu, ssum, 2);
            const float inv = 1.0f / ssum;
            #pragma unroll
            for (int j = 0; j < 8; j++) {
                acc[j][2 * h] *= inv; acc[j][2 * h + 1] *= inv;
            }
        }
    }

    // Permute accumulator frags -> A frags of P (verified recipe from R4),
    // then store coalesced to Pg.
    {
        const int srcA = (lane & 28) | (q4 >> 1);
        const int srcB = srcA | 2;
        const bool odd = (q4 & 1) != 0;
        float4* pgp = (float4*)&Pg[((((size_t)(l0 + l) * 4 + strip) * 8) * 32 + lane) * 4];
        #pragma unroll
        for (int s = 0; s < 8; s++) {
            const float v0 = __shfl_sync(0xffffffffu, acc[s][0], srcA);
            const float v1 = __shfl_sync(0xffffffffu, acc[s][1], srcA);
            const float v2 = __shfl_sync(0xffffffffu, acc[s][2], srcA);
            const float v3 = __shfl_sync(0xffffffffu, acc[s][3], srcA);
            const float w0 = __shfl_sync(0xffffffffu, acc[s][0], srcB);
            const float w1 = __shfl_sync(0xffffffffu, acc[s][1], srcB);
            const float w2 = __shfl_sync(0xffffffffu, acc[s][2], srcB);
            const float w3 = __shfl_sync(0xffffffffu, acc[s][3], srcB);
            float4 pv;
            pv.x = odd ? v1 : v0;   // P[r0][8s+q4]
            pv.y = odd ? v3 : v2;   // P[r0+8][8s+q4]
            pv.z = odd ? w1 : w0;   // P[r0][8s+q4+4]
            pv.w = odd ? w3 : w2;   // P[r0+8][8s+q4+4]
            pgp[s * 32] = pv;
        }
    }
}

// ============================ K2: out = x + P q ==============================
__global__ void __launch_bounds__(NT, 1)
k2_apply(const float* __restrict__ x, float* __restrict__ out) {
    extern __shared__ float sm[];
    float* stage = sm;
    float* msg   = sm + BUF;

    const int t = threadIdx.x, lane = t & 31, w = t >> 5;
    const int l = w >> 2, strip = w & 3;
    const int l0 = blockIdx.x * LT;
    const int r0 = lane >> 2, q4 = lane & 3;
    const int sb = t & 63, sc = t >> 6;

    // P A-frags: 8 coalesced LDG.128, 32 regs, held for the whole kernel.
    float4 pa[8];
    {
        const float4* pgp =
            (const float4*)&Pg[((((size_t)(l0 + l) * 4 + strip) * 8) * 32 + lane) * 4];
        #pragma unroll
        for (int s = 0; s < 8; s++) pa[s] = pgp[s * 32];
    }

    float4 v[2][2];
    ldg_chunk(x, v, 0, l0, sb, sc);

    #pragma unroll 1
    for (int ch = 0; ch < NCH; ch++) {
        sts_chunk(stage, v, sb, sc);
        __syncthreads();                       // stage(ch) visible

        const float* pl = stage + l * PLANE;

        // Residual pre-load: macc starts at x[n][c][l] so out = accumulate.
        float macc[4][4];
        #pragma unroll
        for (int j2 = 0; j2 < 4; j2++) {
            const float* xp = pl + (strip * 16 + r0) * PR + 8 * j2 + 2 * q4;
            macc[j2][0] = xp[0];          macc[j2][1] = xp[1];
            macc[j2][2] = xp[8 * PR];     macc[j2][3] = xp[8 * PR + 1];
        }

        // msg += P q : k over m=64 in 8 steps.
        #pragma unroll
        for (int s = 0; s < 8; s++) {
            #pragma unroll
            for (int j2 = 0; j2 < 4; j2++) {
                const float* bp = pl + (8 * s + q4) * PR + 8 * j2 + r0;
                mma_tf32(macc[j2],
                         fbits(pa[s].x), fbits(pa[s].y), fbits(pa[s].z), fbits(pa[s].w),
                         fbits(bp[0]), fbits(bp[4 * PR]));
            }
        }

        // Transpose result through msg smem: [l][n][c] pitch PR.
        #pragma unroll
        for (int j2 = 0; j2 < 4; j2++) {
            float* mp = msg + l * PLANE + (strip * 16 + r0) * PR + 8 * j2 + 2 * q4;
            mp[0] = macc[j2][0];          mp[1] = macc[j2][1];
            mp[8 * PR] = macc[j2][2];     mp[8 * PR + 1] = macc[j2][3];
        }
        __syncthreads();                       // msg ready; compute done with stage

        if (ch + 1 < NCH) ldg_chunk(x, v, (ch + 1) * CCH, l0, sb, sc);

        // Epilogue: out[b][c][l] as two float4 per (b,c).
        const int c0 = ch * CCH;
        #pragma unroll
        for (int k = 0; k < 2; k++) {
            const float* mp = msg + sb * PR + sc + 16 * k;
            float4 o0, o1;
            o0.x = mp[0 * PLANE]; o0.y = mp[1 * PLANE];
            o0.z = mp[2 * PLANE]; o0.w = mp[3 * PLANE];
            o1.x = mp[4 * PLANE]; o1.y = mp[5 * PLANE];
            o1.z = mp[6 * PLANE]; o1.w = mp[7 * PLANE];
            float* op = out + ((size_t)(sb * kC + c0 + sc + 16 * k)) * kL + l0;
            *(float4*)op       = o0;
            *(float4*)(op + 4) = o1;
        }
        __syncthreads();                       // epilogue done with msg
    }
}

}  // namespace

extern "C" void kernel_launch(void* const* d_in, const int* in_sizes, int n_in,
                              void* d_out, int out_size) {
    (void)in_sizes; (void)n_in; (void)out_size;
    const float* x = (const float*)d_in[0];
    float* out     = (float*)d_out;

    cudaFuncSetAttribute(k1_scores,
                         cudaFuncAttributeMaxDynamicSharedMemorySize, SMEM_BYTES);
    cudaFuncSetAttribute(k2_apply,
                         cudaFuncAttributeMaxDynamicSharedMemorySize, SMEM_BYTES);

    k1_scores<<<kL / LT, NT, SMEM_BYTES>>>(x);
    k2_apply<<<kL / LT, NT, SMEM_BYTES>>>(x, out);
}

// round 7
// speedup vs baseline: 1.5892x; 1.5892x over previous
#include <cuda_runtime.h>
#include <cstdint>

// AttentionalPropagation R6: transpose-based pipeline.
// Every prior design bottomed out at ~0.9 TB/s because x[B,C,L] forces 32B
// sector requests strided 16KB at DRAM. This round makes ALL global traffic
// >=128B contiguous:
//   K0: x[B,C,L] -> xT[L,B,C]           (tiled transpose)
//   K1: P = softmax(qq^T/sqrt(C)) from xT; P -> Pg fragment scratch
//   K2: out_T[L,B,C] = xT + P q          (residual preloaded in accumulator)
//   K3: out_T -> out[B,C,L]              (tiled transpose)
// K1/K2 mma + softmax + fragment permute logic identical to the numerically
// verified R5 kernels; only staging/epilogue addressing changed.

namespace {

constexpr int kB  = 64;
constexpr int kC  = 512;
constexpr int kL  = 4096;
constexpr int kBC = kB * kC;           // 32768
constexpr int LT  = 8;
constexpr int CCH = 32;
constexpr int NCH = kC / CCH;          // 16
constexpr int NT  = 1024;              // 32 warps = 4 per l

constexpr int PR    = 37;              // words per b-row (32 data + 5 pad)
constexpr int PLANE = kB * PR;         // 2368
constexpr int BUF   = LT * PLANE;      // 18944
constexpr int SMEM_BYTES = 2 * BUF * 4;  // 151552 B

// Scratch (static device arrays; no allocation APIs).
__device__ float xT_g [(size_t)kL * kBC];    // 512 MB  [L][B][C]
__device__ float outT_g[(size_t)kL * kBC];   // 512 MB  [L][B][C]
__device__ float Pg[(size_t)kL * 4 * 8 * 32 * 4];   // 64 MB P fragments

__device__ __forceinline__ uint32_t fbits(float f) { return __float_as_uint(f); }

__device__ __forceinline__ void mma_tf32(float d[4],
                                         uint32_t a0, uint32_t a1, uint32_t a2, uint32_t a3,
                                         uint32_t b0, uint32_t b1) {
    asm volatile(
        "mma.sync.aligned.m16n8k8.row.col.f32.tf32.tf32.f32 "
        "{%0,%1,%2,%3}, {%4,%5,%6,%7}, {%8,%9}, {%0,%1,%2,%3};"
        : "+f"(d[0]), "+f"(d[1]), "+f"(d[2]), "+f"(d[3])
        : "r"(a0), "r"(a1), "r"(a2), "r"(a3), "r"(b0), "r"(b1));
}

// ---------------- 64x64 tiled transpose (both sides 256B-contiguous) --------
__device__ __forceinline__ void transpose_body(const float* __restrict__ src,
                                               float* __restrict__ dst,
                                               int src_cols, int dst_cols) {
    __shared__ float tile[64][67];     // pitch 67: STS conflict-free, LDS 2-way
    const int C0 = blockIdx.x * 64;    // src col block
    const int R0 = blockIdx.y * 64;    // src row block
    const int t = threadIdx.x;
    const int row = t >> 2, seg = t & 3;

    const float* sp = src + (size_t)(R0 + row) * src_cols + C0 + seg * 16;
    float4 a0 = ((const float4*)sp)[0];
    float4 a1 = ((const float4*)sp)[1];
    float4 a2 = ((const float4*)sp)[2];
    float4 a3 = ((const float4*)sp)[3];
    float* tr = &tile[row][seg * 16];
    tr[0]=a0.x; tr[1]=a0.y; tr[2]=a0.z; tr[3]=a0.w;
    tr[4]=a1.x; tr[5]=a1.y; tr[6]=a1.z; tr[7]=a1.w;
    tr[8]=a2.x; tr[9]=a2.y; tr[10]=a2.z; tr[11]=a2.w;
    tr[12]=a3.x; tr[13]=a3.y; tr[14]=a3.z; tr[15]=a3.w;
    __syncthreads();

    float o[16];
    #pragma unroll
    for (int k = 0; k < 16; k++) o[k] = tile[seg * 16 + k][row];
    float* dp = dst + (size_t)(C0 + row) * dst_cols + R0 + seg * 16;
    ((float4*)dp)[0] = make_float4(o[0], o[1], o[2], o[3]);
    ((float4*)dp)[1] = make_float4(o[4], o[5], o[6], o[7]);
    ((float4*)dp)[2] = make_float4(o[8], o[9], o[10], o[11]);
    ((float4*)dp)[3] = make_float4(o[12], o[13], o[14], o[15]);
}

__global__ void __launch_bounds__(256) k0_transpose(const float* __restrict__ x) {
    transpose_body(x, xT_g, kL, kBC);      // grid (kL/64, kBC/64)
}
__global__ void __launch_bounds__(256) k3_transpose(float* __restrict__ out) {
    transpose_body(outT_g, out, kBC, kL);  // grid (kBC/64, kL/64)
}

// ------------- staging: xT chunk -> smem [l][b][c] pitch 37 -----------------
// thread t: s = t>>1 (segment: l = s>>6, b = s&63), h = t&1 (64B half of 128B)
__device__ __forceinline__ void ldg_chunk(float4 v[4], int c0, int l0, int s, int h) {
    const float* gp = xT_g + ((size_t)((l0 + (s >> 6)) * kB + (s & 63)) * kC)
                      + c0 + h * 16;
    v[0] = ((const float4*)gp)[0];
    v[1] = ((const float4*)gp)[1];
    v[2] = ((const float4*)gp)[2];
    v[3] = ((const float4*)gp)[3];
}
__device__ __forceinline__ void sts_chunk(float* buf, const float4 v[4], int s, int h) {
    float* sp = buf + (s >> 6) * PLANE + (s & 63) * PR + h * 16;
    sp[0]=v[0].x; sp[1]=v[0].y; sp[2]=v[0].z; sp[3]=v[0].w;
    sp[4]=v[1].x; sp[5]=v[1].y; sp[6]=v[1].z; sp[7]=v[1].w;
    sp[8]=v[2].x; sp[9]=v[2].y; sp[10]=v[2].z; sp[11]=v[2].w;
    sp[12]=v[3].x; sp[13]=v[3].y; sp[14]=v[3].z; sp[15]=v[3].w;
}

// ============================ K1: P = softmax(qq^T/sqrt(C)) =================
__global__ void __launch_bounds__(NT, 1)
k1_scores() {
    extern __shared__ float sm[];
    const int t = threadIdx.x, lane = t & 31, w = t >> 5;
    const int l = w >> 2, strip = w & 3;
    const int l0 = blockIdx.x * LT;
    const int r0 = lane >> 2, q4 = lane & 3;
    const int s = t >> 1, h = t & 1;

    float acc[8][4];
    #pragma unroll
    for (int j = 0; j < 8; j++)
        #pragma unroll
        for (int i = 0; i < 4; i++) acc[j][i] = 0.0f;

    float4 v[4];
    ldg_chunk(v, 0, l0, s, h);
    sts_chunk(sm, v, s, h);
    __syncthreads();

    #pragma unroll 1
    for (int ch = 0; ch < NCH; ch++) {
        if (ch + 1 < NCH) ldg_chunk(v, (ch + 1) * CCH, l0, s, h);
        const float* pl = sm + (ch & 1) * BUF + l * PLANE;
        #pragma unroll
        for (int sk = 0; sk < 4; sk++) {
            const int ca = 8 * sk + q4;
            const float* ap = pl + (strip * 16 + r0) * PR + ca;
            const uint32_t a0 = fbits(ap[0]);
            const uint32_t a1 = fbits(ap[8 * PR]);
            const uint32_t a2 = fbits(ap[4]);
            const uint32_t a3 = fbits(ap[8 * PR + 4]);
            #pragma unroll
            for (int j = 0; j < 8; j++) {
                const float* bp = pl + (8 * j + r0) * PR + ca;
                mma_tf32(acc[j], a0, a1, a2, a3, fbits(bp[0]), fbits(bp[4]));
            }
        }
        if (ch + 1 < NCH) sts_chunk(sm + ((ch + 1) & 1) * BUF, v, s, h);
        __syncthreads();
    }

    // Softmax (warp-local rows; reductions over the q4 quad).
    {
        const float isc = 0.044194173824159216f;   // 1/sqrt(512)
        #pragma unroll
        for (int hh = 0; hh < 2; hh++) {
            float mx = -1e30f;
            #pragma unroll
            for (int j = 0; j < 8; j++) {
                acc[j][2 * hh]     *= isc;
                acc[j][2 * hh + 1] *= isc;
                mx = fmaxf(mx, fmaxf(acc[j][2 * hh], acc[j][2 * hh + 1]));
            }
            mx = fmaxf(mx, __shfl_xor_sync(0xffffffffu, mx, 1));
            mx = fmaxf(mx, __shfl_xor_sync(0xffffffffu, mx, 2));
            float ssum = 0.0f;
            #pragma unroll
            for (int j = 0; j < 8; j++) {
                const float e0 = __expf(acc[j][2 * hh] - mx);
                const float e1 = __expf(acc[j][2 * hh + 1] - mx);
                acc[j][2 * hh] = e0; acc[j][2 * hh + 1] = e1;
                ssum += e0 + e1;
            }
            ssum += __shfl_xor_sync(0xffffffffu, ssum, 1);
            ssum += __shfl_xor_sync(0xffffffffu, ssum, 2);
            const float inv = 1.0f / ssum;
            #pragma unroll
            for (int j = 0; j < 8; j++) {
                acc[j][2 * hh] *= inv; acc[j][2 * hh + 1] *= inv;
            }
        }
    }

    // Permute accumulator frags -> A frags of P; coalesced store to Pg.
    {
        const int srcA = (lane & 28) | (q4 >> 1);
        const int srcB = srcA | 2;
        const bool odd = (q4 & 1) != 0;
        float4* pgp = (float4*)&Pg[((((size_t)(l0 + l) * 4 + strip) * 8) * 32 + lane) * 4];
        #pragma unroll
        for (int sk = 0; sk < 8; sk++) {
            const float v0 = __shfl_sync(0xffffffffu, acc[sk][0], srcA);
            const float v1 = __shfl_sync(0xffffffffu, acc[sk][1], srcA);
            const float v2 = __shfl_sync(0xffffffffu, acc[sk][2], srcA);
            const float v3 = __shfl_sync(0xffffffffu, acc[sk][3], srcA);
            const float w0 = __shfl_sync(0xffffffffu, acc[sk][0], srcB);
            const float w1 = __shfl_sync(0xffffffffu, acc[sk][1], srcB);
            const float w2 = __shfl_sync(0xffffffffu, acc[sk][2], srcB);
            const float w3 = __shfl_sync(0xffffffffu, acc[sk][3], srcB);
            float4 pv;
            pv.x = odd ? v1 : v0;
            pv.y = odd ? v3 : v2;
            pv.z = odd ? w1 : w0;
            pv.w = odd ? w3 : w2;
            pgp[sk * 32] = pv;
        }
    }
}

// ============================ K2: out_T = xT + P q ==========================
__global__ void __launch_bounds__(NT, 1)
k2_apply() {
    extern __shared__ float sm[];
    float* stage = sm;
    float* msg   = sm + BUF;

    const int t = threadIdx.x, lane = t & 31, w = t >> 5;
    const int l = w >> 2, strip = w & 3;
    const int l0 = blockIdx.x * LT;
    const int r0 = lane >> 2, q4 = lane & 3;
    const int s = t >> 1, h = t & 1;

    float4 pa[8];
    {
        const float4* pgp =
            (const float4*)&Pg[((((size_t)(l0 + l) * 4 + strip) * 8) * 32 + lane) * 4];
        #pragma unroll
        for (int sk = 0; sk < 8; sk++) pa[sk] = pgp[sk * 32];
    }

    float4 v[4];
    ldg_chunk(v, 0, l0, s, h);

    #pragma unroll 1
    for (int ch = 0; ch < NCH; ch++) {
        sts_chunk(stage, v, s, h);
        __syncthreads();

        const float* pl = stage + l * PLANE;

        // Residual preload: out = x + P q via accumulate.
        float macc[4][4];
        #pragma unroll
        for (int j2 = 0; j2 < 4; j2++) {
            const float* xp = pl + (strip * 16 + r0) * PR + 8 * j2 + 2 * q4;
            macc[j2][0] = xp[0];          macc[j2][1] = xp[1];
            macc[j2][2] = xp[8 * PR];     macc[j2][3] = xp[8 * PR + 1];
        }

        #pragma unroll
        for (int sk = 0; sk < 8; sk++) {
            #pragma unroll
            for (int j2 = 0; j2 < 4; j2++) {
                const float* bp = pl + (8 * sk + q4) * PR + 8 * j2 + r0;
                mma_tf32(macc[j2],
                         fbits(pa[sk].x), fbits(pa[sk].y), fbits(pa[sk].z), fbits(pa[sk].w),
                         fbits(bp[0]), fbits(bp[4 * PR]));
            }
        }

        #pragma unroll
        for (int j2 = 0; j2 < 4; j2++) {
            float* mp = msg + l * PLANE + (strip * 16 + r0) * PR + 8 * j2 + 2 * q4;
            mp[0] = macc[j2][0];          mp[1] = macc[j2][1];
            mp[8 * PR] = macc[j2][2];     mp[8 * PR + 1] = macc[j2][3];
        }
        __syncthreads();

        if (ch + 1 < NCH) ldg_chunk(v, (ch + 1) * CCH, l0, s, h);

        // Epilogue: contiguous 64B store per thread into out_T.
        {
            const float* mp = msg + (s >> 6) * PLANE + (s & 63) * PR + h * 16;
            float* op = outT_g + ((size_t)((l0 + (s >> 6)) * kB + (s & 63)) * kC)
                        + ch * CCH + h * 16;
            ((float4*)op)[0] = make_float4(mp[0],  mp[1],  mp[2],  mp[3]);
            ((float4*)op)[1] = make_float4(mp[4],  mp[5],  mp[6],  mp[7]);
            ((float4*)op)[2] = make_float4(mp[8],  mp[9],  mp[10], mp[11]);
            ((float4*)op)[3] = make_float4(mp[12], mp[13], mp[14], mp[15]);
        }
        __syncthreads();
    }
}

}  // namespace

extern "C" void kernel_launch(void* const* d_in, const int* in_sizes, int n_in,
                              void* d_out, int out_size) {
    (void)in_sizes; (void)n_in; (void)out_size;
    const float* x = (const float*)d_in[0];
    float* out     = (float*)d_out;

    cudaFuncSetAttribute(k1_scores,
                         cudaFuncAttributeMaxDynamicSharedMemorySize, SMEM_BYTES);
    cudaFuncSetAttribute(k2_apply,
                         cudaFuncAttributeMaxDynamicSharedMemorySize, SMEM_BYTES);

    dim3 g0(kL / 64, kBC / 64);        // x -> xT
    k0_transpose<<<g0, 256>>>(x);
    k1_scores<<<kL / LT, NT, SMEM_BYTES>>>();
    k2_apply<<<kL / LT, NT, SMEM_BYTES>>>();
    dim3 g3(kBC / 64, kL / 64);        // out_T -> out
    k3_transpose<<<g3, 256>>>(out);
}

// round 8
// speedup vs baseline: 1.6851x; 1.0603x over previous
#include <cuda_runtime.h>
#include <cstdint>

// AttentionalPropagation R7: blocked-layout pipeline.
//   K0: x[B,C,L] -> xblk[L/8][B][C][8]     (all dst stores 2KB-contiguous)
//   K1: P = softmax(qq^T/sqrt(C)) from xblk; P -> Pg fragment scratch
//   K2: outblk = xblk + P q (blocked layout; residual preloaded in accum)
//   K3: outblk -> out[B,C,L]
// K1/K2 chunk loads are 64 x 1KB contiguous runs (vs 128B stride-2KB in R6),
// and the lt-innermost layout makes the smem plane-scatter STS conflict-free.
// mma / softmax / fragment-permute logic identical to the verified R5/R6 code.

namespace {

constexpr int kB  = 64;
constexpr int kC  = 512;
constexpr int kL  = 4096;
constexpr int LT  = 8;
constexpr int CCH = 32;
constexpr int NCH = kC / CCH;          // 16
constexpr int NT  = 1024;              // 32 warps = 4 per l

constexpr int PR    = 37;              // words per b-row in smem (32 data + 5 pad)
constexpr int PLANE = kB * PR;         // 2368
constexpr int BUF   = LT * PLANE;      // 18944
constexpr int SMEM_BYTES = 2 * BUF * 4;  // 151552 B

// Blocked scratch: [blk = l/8][b][c][lt] ; 512MB each.
__device__ float xblk_g [(size_t)(kL / 8) * kB * kC * 8];
__device__ float oblk_g [(size_t)(kL / 8) * kB * kC * 8];
__device__ float Pg[(size_t)kL * 4 * 8 * 32 * 4];   // 64 MB P fragments

__device__ __forceinline__ uint32_t fbits(float f) { return __float_as_uint(f); }

__device__ __forceinline__ void mma_tf32(float d[4],
                                         uint32_t a0, uint32_t a1, uint32_t a2, uint32_t a3,
                                         uint32_t b0, uint32_t b1) {
    asm volatile(
        "mma.sync.aligned.m16n8k8.row.col.f32.tf32.tf32.f32 "
        "{%0,%1,%2,%3}, {%4,%5,%6,%7}, {%8,%9}, {%0,%1,%2,%3};"
        : "+f"(d[0]), "+f"(d[1]), "+f"(d[2]), "+f"(d[3])
        : "r"(a0), "r"(a1), "r"(a2), "r"(a3), "r"(b0), "r"(b1));
}

// ==================== K0: x[B,C,L] -> xblk[blk][b][c][lt] ====================
// CTA: (l0 = 64-block, c0 = 64-block, b). Tile 64c x 64l in smem.
__global__ void __launch_bounds__(256)
k0_pack(const float* __restrict__ x) {
    __shared__ float tile[64][65];
    const int l0 = blockIdx.x * 64;
    const int c0 = blockIdx.y * 64;
    const int b  = blockIdx.z;
    const int t  = threadIdx.x;

    // Read: thread (c = t>>2, ls = (t&3)*16): 64B contiguous along l.
    {
        const int c = t >> 2, ls = (t & 3) * 16;
        const float* gp = x + ((size_t)(b * kC + c0 + c)) * kL + l0 + ls;
        #pragma unroll
        for (int i = 0; i < 4; i++) {
            const float4 v = ((const float4*)gp)[i];
            float* tp = &tile[c][ls + i * 4];
            tp[0] = v.x; tp[1] = v.y; tp[2] = v.z; tp[3] = v.w;
        }
    }
    __syncthreads();

    // Write: warp w8 handles blk (l0/8 + w8); lane writes 16 contiguous floats
    // = (c = 2*lane + k/8, lt = k%8). Warp covers 2KB contiguous.
    {
        const int w8 = t >> 5, lane = t & 31;
        float o[16];
        #pragma unroll
        for (int k = 0; k < 16; k++)
            o[k] = tile[2 * lane + (k >> 3)][w8 * 8 + (k & 7)];
        float* dp = xblk_g + (((size_t)((l0 / 8 + w8) * kB + b)) * kC + c0 + 2 * lane) * 8;
        ((float4*)dp)[0] = make_float4(o[0],  o[1],  o[2],  o[3]);
        ((float4*)dp)[1] = make_float4(o[4],  o[5],  o[6],  o[7]);
        ((float4*)dp)[2] = make_float4(o[8],  o[9],  o[10], o[11]);
        ((float4*)dp)[3] = make_float4(o[12], o[13], o[14], o[15]);
    }
}

// ==================== K3: oblk[blk][b][c][lt] -> out[B,C,L] ==================
__global__ void __launch_bounds__(256)
k3_unpack(float* __restrict__ out) {
    __shared__ float tile[64][65];
    const int l0 = blockIdx.x * 64;
    const int c0 = blockIdx.y * 64;
    const int b  = blockIdx.z;
    const int t  = threadIdx.x;

    // Read: warp w8 loads blk (l0/8 + w8), lane 16 contiguous floats.
    {
        const int w8 = t >> 5, lane = t & 31;
        const float* sp = oblk_g + (((size_t)((l0 / 8 + w8) * kB + b)) * kC + c0 + 2 * lane) * 8;
        const float4 v0 = ((const float4*)sp)[0];
        const float4 v1 = ((const float4*)sp)[1];
        const float4 v2 = ((const float4*)sp)[2];
        const float4 v3 = ((const float4*)sp)[3];
        const float o[16] = {v0.x,v0.y,v0.z,v0.w, v1.x,v1.y,v1.z,v1.w,
                             v2.x,v2.y,v2.z,v2.w, v3.x,v3.y,v3.z,v3.w};
        #pragma unroll
        for (int k = 0; k < 16; k++)
            tile[2 * lane + (k >> 3)][w8 * 8 + (k & 7)] = o[k];
    }
    __syncthreads();

    // Write: thread (c = t>>2, ls = (t&3)*16): 64B contiguous along l.
    {
        const int c = t >> 2, ls = (t & 3) * 16;
        float* gp = out + ((size_t)(b * kC + c0 + c)) * kL + l0 + ls;
        #pragma unroll
        for (int i = 0; i < 4; i++) {
            const float* tp = &tile[c][ls + i * 4];
            ((float4*)gp)[i] = make_float4(tp[0], tp[1], tp[2], tp[3]);
        }
    }
}

// --------- staging: xblk chunk -> smem [lt][b][c] pitch 37 ------------------
// thread owns 2 (b,c) pairs: pair p -> b = (t>>5) + 32p, c = t&31.
__device__ __forceinline__ void ldg_chunk(float4 v[2][2], int blk, int c0, int t) {
    #pragma unroll
    for (int p = 0; p < 2; p++) {
        const int b = (t >> 5) + 32 * p;
        const int c = t & 31;
        const float* gp = xblk_g + (((size_t)(blk * kB + b)) * kC + c0 + c) * 8;
        v[p][0] = ((const float4*)gp)[0];
        v[p][1] = ((const float4*)gp)[1];
    }
}
__device__ __forceinline__ void sts_chunk(float* buf, const float4 v[2][2], int t) {
    #pragma unroll
    for (int p = 0; p < 2; p++) {
        float* sp = buf + ((t >> 5) + 32 * p) * PR + (t & 31);
        sp[0 * PLANE] = v[p][0].x; sp[1 * PLANE] = v[p][0].y;
        sp[2 * PLANE] = v[p][0].z; sp[3 * PLANE] = v[p][0].w;
        sp[4 * PLANE] = v[p][1].x; sp[5 * PLANE] = v[p][1].y;
        sp[6 * PLANE] = v[p][1].z; sp[7 * PLANE] = v[p][1].w;
    }
}

// ============================ K1: P = softmax(qq^T/sqrt(C)) =================
__global__ void __launch_bounds__(NT, 1)
k1_scores() {
    extern __shared__ float sm[];
    const int t = threadIdx.x, lane = t & 31, w = t >> 5;
    const int l = w >> 2, strip = w & 3;
    const int blk = blockIdx.x;
    const int r0 = lane >> 2, q4 = lane & 3;

    float acc[8][4];
    #pragma unroll
    for (int j = 0; j < 8; j++)
        #pragma unroll
        for (int i = 0; i < 4; i++) acc[j][i] = 0.0f;

    float4 v[2][2];
    ldg_chunk(v, blk, 0, t);
    sts_chunk(sm, v, t);
    __syncthreads();

    #pragma unroll 1
    for (int ch = 0; ch < NCH; ch++) {
        if (ch + 1 < NCH) ldg_chunk(v, blk, (ch + 1) * CCH, t);
        const float* pl = sm + (ch & 1) * BUF + l * PLANE;
        #pragma unroll
        for (int sk = 0; sk < 4; sk++) {
            const int ca = 8 * sk + q4;
            const float* ap = pl + (strip * 16 + r0) * PR + ca;
            const uint32_t a0 = fbits(ap[0]);
            const uint32_t a1 = fbits(ap[8 * PR]);
            const uint32_t a2 = fbits(ap[4]);
            const uint32_t a3 = fbits(ap[8 * PR + 4]);
            #pragma unroll
            for (int j = 0; j < 8; j++) {
                const float* bp = pl + (8 * j + r0) * PR + ca;
                mma_tf32(acc[j], a0, a1, a2, a3, fbits(bp[0]), fbits(bp[4]));
            }
        }
        if (ch + 1 < NCH) sts_chunk(sm + ((ch + 1) & 1) * BUF, v, t);
        __syncthreads();
    }

    // Softmax (warp-local rows; reductions over the q4 quad).
    {
        const float isc = 0.044194173824159216f;   // 1/sqrt(512)
        #pragma unroll
        for (int hh = 0; hh < 2; hh++) {
            float mx = -1e30f;
            #pragma unroll
            for (int j = 0; j < 8; j++) {
                acc[j][2 * hh]     *= isc;
                acc[j][2 * hh + 1] *= isc;
                mx = fmaxf(mx, fmaxf(acc[j][2 * hh], acc[j][2 * hh + 1]));
            }
            mx = fmaxf(mx, __shfl_xor_sync(0xffffffffu, mx, 1));
            mx = fmaxf(mx, __shfl_xor_sync(0xffffffffu, mx, 2));
            float ssum = 0.0f;
            #pragma unroll
            for (int j = 0; j < 8; j++) {
                const float e0 = __expf(acc[j][2 * hh] - mx);
                const float e1 = __expf(acc[j][2 * hh + 1] - mx);
                acc[j][2 * hh] = e0; acc[j][2 * hh + 1] = e1;
                ssum += e0 + e1;
            }
            ssum += __shfl_xor_sync(0xffffffffu, ssum, 1);
            ssum += __shfl_xor_sync(0xffffffffu, ssum, 2);
            const float inv = 1.0f / ssum;
            #pragma unroll
            for (int j = 0; j < 8; j++) {
                acc[j][2 * hh] *= inv; acc[j][2 * hh + 1] *= inv;
            }
        }
    }

    // Permute accumulator frags -> A frags of P; coalesced store to Pg.
    {
        const int srcA = (lane & 28) | (q4 >> 1);
        const int srcB = srcA | 2;
        const bool odd = (q4 & 1) != 0;
        float4* pgp = (float4*)&Pg[((((size_t)(blk * LT + l) * 4 + strip) * 8) * 32 + lane) * 4];
        #pragma unroll
        for (int sk = 0; sk < 8; sk++) {
            const float v0 = __shfl_sync(0xffffffffu, acc[sk][0], srcA);
            const float v1 = __shfl_sync(0xffffffffu, acc[sk][1], srcA);
            const float v2 = __shfl_sync(0xffffffffu, acc[sk][2], srcA);
            const float v3 = __shfl_sync(0xffffffffu, acc[sk][3], srcA);
            const float w0 = __shfl_sync(0xffffffffu, acc[sk][0], srcB);
            const float w1 = __shfl_sync(0xffffffffu, acc[sk][1], srcB);
            const float w2 = __shfl_sync(0xffffffffu, acc[sk][2], srcB);
            const float w3 = __shfl_sync(0xffffffffu, acc[sk][3], srcB);
            float4 pv;
            pv.x = odd ? v1 : v0;
            pv.y = odd ? v3 : v2;
            pv.z = odd ? w1 : w0;
            pv.w = odd ? w3 : w2;
            pgp[sk * 32] = pv;
        }
    }
}

// ============================ K2: oblk = xblk + P q ==========================
__global__ void __launch_bounds__(NT, 1)
k2_apply() {
    extern __shared__ float sm[];
    float* stage = sm;
    float* msg   = sm + BUF;

    const int t = threadIdx.x, lane = t & 31, w = t >> 5;
    const int l = w >> 2, strip = w & 3;
    const int blk = blockIdx.x;
    const int r0 = lane >> 2, q4 = lane & 3;

    float4 pa[8];
    {
        const float4* pgp =
            (const float4*)&Pg[((((size_t)(blk * LT + l) * 4 + strip) * 8) * 32 + lane) * 4];
        #pragma unroll
        for (int sk = 0; sk < 8; sk++) pa[sk] = pgp[sk * 32];
    }

    float4 v[2][2];
    ldg_chunk(v, blk, 0, t);

    #pragma unroll 1
    for (int ch = 0; ch < NCH; ch++) {
        sts_chunk(stage, v, t);
        __syncthreads();

        const float* pl = stage + l * PLANE;

        // Residual preload: out = x + P q via accumulate.
        float macc[4][4];
        #pragma unroll
        for (int j2 = 0; j2 < 4; j2++) {
            const float* xp = pl + (strip * 16 + r0) * PR + 8 * j2 + 2 * q4;
            macc[j2][0] = xp[0];          macc[j2][1] = xp[1];
            macc[j2][2] = xp[8 * PR];     macc[j2][3] = xp[8 * PR + 1];
        }

        #pragma unroll
        for (int sk = 0; sk < 8; sk++) {
            #pragma unroll
            for (int j2 = 0; j2 < 4; j2++) {
                const float* bp = pl + (8 * sk + q4) * PR + 8 * j2 + r0;
                mma_tf32(macc[j2],
                         fbits(pa[sk].x), fbits(pa[sk].y), fbits(pa[sk].z), fbits(pa[sk].w),
                         fbits(bp[0]), fbits(bp[4 * PR]));
            }
        }

        #pragma unroll
        for (int j2 = 0; j2 < 4; j2++) {
            float* mp = msg + l * PLANE + (strip * 16 + r0) * PR + 8 * j2 + 2 * q4;
            mp[0] = macc[j2][0];          mp[1] = macc[j2][1];
            mp[8 * PR] = macc[j2][2];     mp[8 * PR + 1] = macc[j2][3];
        }
        __syncthreads();

        if (ch + 1 < NCH) ldg_chunk(v, blk, (ch + 1) * CCH, t);

        // Epilogue: thread writes 2 x 32B contiguous (1KB per warp) to oblk.
        {
            const int c0 = ch * CCH;
            #pragma unroll
            for (int p = 0; p < 2; p++) {
                const int b = (t >> 5) + 32 * p;
                const int c = t & 31;
                const float* mp = msg + b * PR + c;
                float* op = oblk_g + (((size_t)(blk * kB + b)) * kC + c0 + c) * 8;
                ((float4*)op)[0] = make_float4(mp[0 * PLANE], mp[1 * PLANE],
                                               mp[2 * PLANE], mp[3 * PLANE]);
                ((float4*)op)[1] = make_float4(mp[4 * PLANE], mp[5 * PLANE],
                                               mp[6 * PLANE], mp[7 * PLANE]);
            }
        }
        __syncthreads();
    }
}

}  // namespace

extern "C" void kernel_launch(void* const* d_in, const int* in_sizes, int n_in,
                              void* d_out, int out_size) {
    (void)in_sizes; (void)n_in; (void)out_size;
    const float* x = (const float*)d_in[0];
    float* out     = (float*)d_out;

    cudaFuncSetAttribute(k1_scores,
                         cudaFuncAttributeMaxDynamicSharedMemorySize, SMEM_BYTES);
    cudaFuncSetAttribute(k2_apply,
                         cudaFuncAttributeMaxDynamicSharedMemorySize, SMEM_BYTES);

    dim3 gt(kL / 64, kC / 64, kB);     // 64 x 8 x 64
    k0_pack<<<gt, 256>>>(x);
    k1_scores<<<kL / LT, NT, SMEM_BYTES>>>();
    k2_apply<<<kL / LT, NT, SMEM_BYTES>>>();
    k3_unpack<<<gt, 256>>>(out);
}

// round 9
// speedup vs baseline: 2.1476x; 1.2745x over previous
#include <cuda_runtime.h>
#include <cstdint>

// AttentionalPropagation R8: small-CTA latency-overlapped pipeline.
//   K0: x[B,C,L] -> xT[L,B,C]            (64x64 tiled transpose, proven)
//   K1: per-l CTA (128 thr): P = softmax(qq^T/sqrt(C)); P -> Pg fragments
//   K2: per-l CTA (128 thr): outT = xT + P q (residual preloaded in accum)
//   K3: outT -> out[B,C,L]
// R7 finding: monolithic 1024-thread CTAs were barrier-latency bound (1 CTA/SM,
// ~1us exposed per chunk). R8 uses 12 (K1) / 8 (K2) independent 4-warp CTAs
// per SM + cp.async double buffering so stalls in one CTA are filled by others.
// Smem pitch 36: pass-1 fragment LDS exactly conflict-free, rest <=2-way.

namespace {

constexpr int kB  = 64;
constexpr int kC  = 512;
constexpr int kL  = 4096;
constexpr int kBC = kB * kC;
constexpr int CCH = 32;
constexpr int NCH = kC / CCH;        // 16

constexpr int PR    = 36;            // words per b-row (16B-aligned rows)
constexpr int PLANE = kB * PR;       // 2304 words = 9216 B
constexpr int SMEM_K1 = 2 * PLANE * 4;   // 18432 B
constexpr int SMEM_K2 = 3 * PLANE * 4;   // 27648 B

__device__ float xT_g[(size_t)kL * kBC];            // 512 MB [L][B][C]
__device__ float oT_g[(size_t)kL * kBC];            // 512 MB [L][B][C]
__device__ float Pg[(size_t)kL * 4 * 8 * 32 * 4];   // 64 MB P fragments

__device__ __forceinline__ uint32_t fbits(float f) { return __float_as_uint(f); }

__device__ __forceinline__ void mma_tf32(float d[4],
                                         uint32_t a0, uint32_t a1, uint32_t a2, uint32_t a3,
                                         uint32_t b0, uint32_t b1) {
    asm volatile(
        "mma.sync.aligned.m16n8k8.row.col.f32.tf32.tf32.f32 "
        "{%0,%1,%2,%3}, {%4,%5,%6,%7}, {%8,%9}, {%0,%1,%2,%3};"
        : "+f"(d[0]), "+f"(d[1]), "+f"(d[2]), "+f"(d[3])
        : "r"(a0), "r"(a1), "r"(a2), "r"(a3), "r"(b0), "r"(b1));
}

__device__ __forceinline__ void cp16(uint32_t dst, const void* src) {
    asm volatile("cp.async.ca.shared.global [%0], [%1], 16;" :: "r"(dst), "l"(src));
}
__device__ __forceinline__ void cp_commit() {
    asm volatile("cp.async.commit_group;" ::: "memory");
}
template <int N>
__device__ __forceinline__ void cp_wait() {
    asm volatile("cp.async.wait_group %0;" :: "n"(N) : "memory");
}

// ---------------- 64x64 tiled transpose (proven R6/R7 code) -----------------
__device__ __forceinline__ void transpose_body(const float* __restrict__ src,
                                               float* __restrict__ dst,
                                               int src_cols, int dst_cols) {
    __shared__ float tile[64][67];
    const int C0 = blockIdx.x * 64;
    const int R0 = blockIdx.y * 64;
    const int t = threadIdx.x;
    const int row = t >> 2, seg = t & 3;

    const float* sp = src + (size_t)(R0 + row) * src_cols + C0 + seg * 16;
    float4 a0 = ((const float4*)sp)[0];
    float4 a1 = ((const float4*)sp)[1];
    float4 a2 = ((const float4*)sp)[2];
    float4 a3 = ((const float4*)sp)[3];
    float* tr = &tile[row][seg * 16];
    tr[0]=a0.x; tr[1]=a0.y; tr[2]=a0.z; tr[3]=a0.w;
    tr[4]=a1.x; tr[5]=a1.y; tr[6]=a1.z; tr[7]=a1.w;
    tr[8]=a2.x; tr[9]=a2.y; tr[10]=a2.z; tr[11]=a2.w;
    tr[12]=a3.x; tr[13]=a3.y; tr[14]=a3.z; tr[15]=a3.w;
    __syncthreads();

    float o[16];
    #pragma unroll
    for (int k = 0; k < 16; k++) o[k] = tile[seg * 16 + k][row];
    float* dp = dst + (size_t)(C0 + row) * dst_cols + R0 + seg * 16;
    ((float4*)dp)[0] = make_float4(o[0], o[1], o[2], o[3]);
    ((float4*)dp)[1] = make_float4(o[4], o[5], o[6], o[7]);
    ((float4*)dp)[2] = make_float4(o[8], o[9], o[10], o[11]);
    ((float4*)dp)[3] = make_float4(o[12], o[13], o[14], o[15]);
}

__global__ void __launch_bounds__(256) k0_transpose(const float* __restrict__ x) {
    transpose_body(x, xT_g, kL, kBC);      // grid (kL/64, kBC/64)
}
__global__ void __launch_bounds__(256) k3_transpose(float* __restrict__ out) {
    transpose_body(oT_g, out, kBC, kL);    // grid (kBC/64, kL/64)
}

// -------- per-l chunk staging: xT[l][b][c0..c0+31] -> smem [b][c] pitch 36 ---
// thread t: b = t>>1, h = t&1 owns 64B (16 floats) contiguous.
__device__ __forceinline__ void issue_chunk(uint32_t smbase, int bufsel,
                                            int l, int c0, int t) {
    const int b = t >> 1, h = t & 1;
    const float* src = xT_g + ((size_t)(l * kB + b)) * kC + c0 + h * 16;
    const uint32_t dst = smbase + (uint32_t)(bufsel * PLANE + b * PR + h * 16) * 4u;
    #pragma unroll
    for (int i = 0; i < 4; i++) cp16(dst + 16u * i, src + 4 * i);
}

// ============================ K1: P = softmax(qq^T/sqrt(C)) =================
__global__ void __launch_bounds__(128)
k1_scores() {
    extern __shared__ float sm[];
    const int t = threadIdx.x, lane = t & 31;
    const int strip = t >> 5;              // warp = 16-row strip
    const int l = blockIdx.x;
    const int r0 = lane >> 2, q4 = lane & 3;
    const uint32_t smbase = (uint32_t)__cvta_generic_to_shared(sm);

    float acc[8][4];
    #pragma unroll
    for (int j = 0; j < 8; j++)
        #pragma unroll
        for (int i = 0; i < 4; i++) acc[j][i] = 0.0f;

    issue_chunk(smbase, 0, l, 0, t);
    cp_commit();

    #pragma unroll 1
    for (int ch = 0; ch < NCH; ch++) {
        if (ch) __syncthreads();           // compute(ch-1) done -> its buf reusable
        if (ch + 1 < NCH) {
            issue_chunk(smbase, (ch + 1) & 1, l, (ch + 1) * CCH, t);
            cp_commit();
            cp_wait<1>();
        } else {
            cp_wait<0>();
        }
        __syncthreads();                   // chunk ch visible to all warps
        const float* pl = sm + (ch & 1) * PLANE;
        #pragma unroll
        for (int sk = 0; sk < 4; sk++) {
            const int ca = 8 * sk + q4;
            const float* ap = pl + (strip * 16 + r0) * PR + ca;
            const uint32_t a0 = fbits(ap[0]);
            const uint32_t a1 = fbits(ap[8 * PR]);
            const uint32_t a2 = fbits(ap[4]);
            const uint32_t a3 = fbits(ap[8 * PR + 4]);
            #pragma unroll
            for (int j = 0; j < 8; j++) {
                const float* bp = pl + (8 * j + r0) * PR + ca;
                mma_tf32(acc[j], a0, a1, a2, a3, fbits(bp[0]), fbits(bp[4]));
            }
        }
    }

    // Softmax (warp-local rows; reductions over the q4 quad).
    {
        const float isc = 0.044194173824159216f;   // 1/sqrt(512)
        #pragma unroll
        for (int hh = 0; hh < 2; hh++) {
            float mx = -1e30f;
            #pragma unroll
            for (int j = 0; j < 8; j++) {
                acc[j][2 * hh]     *= isc;
                acc[j][2 * hh + 1] *= isc;
                mx = fmaxf(mx, fmaxf(acc[j][2 * hh], acc[j][2 * hh + 1]));
            }
            mx = fmaxf(mx, __shfl_xor_sync(0xffffffffu, mx, 1));
            mx = fmaxf(mx, __shfl_xor_sync(0xffffffffu, mx, 2));
            float ssum = 0.0f;
            #pragma unroll
            for (int j = 0; j < 8; j++) {
                const float e0 = __expf(acc[j][2 * hh] - mx);
                const float e1 = __expf(acc[j][2 * hh + 1] - mx);
                acc[j][2 * hh] = e0; acc[j][2 * hh + 1] = e1;
                ssum += e0 + e1;
            }
            ssum += __shfl_xor_sync(0xffffffffu, ssum, 1);
            ssum += __shfl_xor_sync(0xffffffffu, ssum, 2);
            const float inv = 1.0f / ssum;
            #pragma unroll
            for (int j = 0; j < 8; j++) {
                acc[j][2 * hh] *= inv; acc[j][2 * hh + 1] *= inv;
            }
        }
    }

    // Permute accumulator frags -> A frags of P; coalesced float4 store to Pg.
    {
        const int srcA = (lane & 28) | (q4 >> 1);
        const int srcB = srcA | 2;
        const bool odd = (q4 & 1) != 0;
        float4* pgp = (float4*)&Pg[((((size_t)l * 4 + strip) * 8) * 32 + lane) * 4];
        #pragma unroll
        for (int sk = 0; sk < 8; sk++) {
            const float v0 = __shfl_sync(0xffffffffu, acc[sk][0], srcA);
            const float v1 = __shfl_sync(0xffffffffu, acc[sk][1], srcA);
            const float v2 = __shfl_sync(0xffffffffu, acc[sk][2], srcA);
            const float v3 = __shfl_sync(0xffffffffu, acc[sk][3], srcA);
            const float w0 = __shfl_sync(0xffffffffu, acc[sk][0], srcB);
            const float w1 = __shfl_sync(0xffffffffu, acc[sk][1], srcB);
            const float w2 = __shfl_sync(0xffffffffu, acc[sk][2], srcB);
            const float w3 = __shfl_sync(0xffffffffu, acc[sk][3], srcB);
            float4 pv;
            pv.x = odd ? v1 : v0;
            pv.y = odd ? v3 : v2;
            pv.z = odd ? w1 : w0;
            pv.w = odd ? w3 : w2;
            pgp[sk * 32] = pv;
        }
    }
}

// ============================ K2: outT = xT + P q ============================
__global__ void __launch_bounds__(128)
k2_apply() {
    extern __shared__ float sm[];
    float* msg = sm + 2 * PLANE;

    const int t = threadIdx.x, lane = t & 31;
    const int strip = t >> 5;
    const int l = blockIdx.x;
    const int r0 = lane >> 2, q4 = lane & 3;
    const uint32_t smbase = (uint32_t)__cvta_generic_to_shared(sm);

    // P A-frags: 8 coalesced float4 loads, held in registers.
    float4 pa[8];
    {
        const float4* pgp =
            (const float4*)&Pg[((((size_t)l * 4 + strip) * 8) * 32 + lane) * 4];
        #pragma unroll
        for (int sk = 0; sk < 8; sk++) pa[sk] = pgp[sk * 32];
    }

    issue_chunk(smbase, 0, l, 0, t);
    cp_commit();

    #pragma unroll 1
    for (int ch = 0; ch < NCH; ch++) {
        if (ch) __syncthreads();           // epilogue(ch-1) done -> bufs reusable
        if (ch + 1 < NCH) {
            issue_chunk(smbase, (ch + 1) & 1, l, (ch + 1) * CCH, t);
            cp_commit();
            cp_wait<1>();
        } else {
            cp_wait<0>();
        }
        __syncthreads();                   // stage(ch) visible
        const float* pl = sm + (ch & 1) * PLANE;

        // Residual preload: out = x + P q via accumulate.
        float macc[4][4];
        #pragma unroll
        for (int j2 = 0; j2 < 4; j2++) {
            const float* xp = pl + (strip * 16 + r0) * PR + 8 * j2 + 2 * q4;
            macc[j2][0] = xp[0];          macc[j2][1] = xp[1];
            macc[j2][2] = xp[8 * PR];     macc[j2][3] = xp[8 * PR + 1];
        }

        #pragma unroll
        for (int sk = 0; sk < 8; sk++) {
            #pragma unroll
            for (int j2 = 0; j2 < 4; j2++) {
                const float* bp = pl + (8 * sk + q4) * PR + 8 * j2 + r0;
                mma_tf32(macc[j2],
                         fbits(pa[sk].x), fbits(pa[sk].y), fbits(pa[sk].z), fbits(pa[sk].w),
                         fbits(bp[0]), fbits(bp[4 * PR]));
            }
        }

        // msg fragments -> smem [n][c] pitch PR.
        #pragma unroll
        for (int j2 = 0; j2 < 4; j2++) {
            float* mp = msg + (strip * 16 + r0) * PR + 8 * j2 + 2 * q4;
            mp[0] = macc[j2][0];          mp[1] = macc[j2][1];
            mp[8 * PR] = macc[j2][2];     mp[8 * PR + 1] = macc[j2][3];
        }
        __syncthreads();                   // msg visible

        // Epilogue: thread writes 64B contiguous to outT.
        {
            const int b = t >> 1, h = t & 1;
            const float* mp = msg + b * PR + h * 16;
            float* op = oT_g + ((size_t)(l * kB + b)) * kC + ch * CCH + h * 16;
            #pragma unroll
            for (int i = 0; i < 4; i++)
                ((float4*)op)[i] = make_float4(mp[4 * i], mp[4 * i + 1],
                                               mp[4 * i + 2], mp[4 * i + 3]);
        }
    }
}

}  // namespace

extern "C" void kernel_launch(void* const* d_in, const int* in_sizes, int n_in,
                              void* d_out, int out_size) {
    (void)in_sizes; (void)n_in; (void)out_size;
    const float* x = (const float*)d_in[0];
    float* out     = (float*)d_out;

    dim3 g0(kL / 64, kBC / 64);
    k0_transpose<<<g0, 256>>>(x);
    k1_scores<<<kL, 128, SMEM_K1>>>();
    k2_apply<<<kL, 128, SMEM_K2>>>();
    dim3 g3(kBC / 64, kL / 64);
    k3_transpose<<<g3, 256>>>(out);
}

// round 10
// speedup vs baseline: 2.2735x; 1.0587x over previous
#include <cuda_runtime.h>
#include <cstdint>

// AttentionalPropagation R9: fused middle stage.
//   K0:  x[B,C,L] -> xT[L,B,C]                  (64x64 tiled transpose)
//   K12: per-l CTA (128 thr): the FULL 64x512 q plane (128KB) is loaded into
//        smem once via 16 progressive cp.async groups; pass 1 (S = qq^T),
//        softmax, register P-permute, then pass 2 (outT = xT + P q) all run
//        against the resident planes. No Pg scratch, no second xT read.
//   K3:  outT -> out[B,C,L]
// mma / softmax / fragment-permute code verbatim from the verified R5-R8
// kernels (rel_err 2.28e-4). Pass-1 fragment LDS conflict-free at pitch 36.

namespace {

constexpr int kB  = 64;
constexpr int kC  = 512;
constexpr int kL  = 4096;
constexpr int kBC = kB * kC;
constexpr int CCH = 32;
constexpr int NCH = kC / CCH;        // 16

constexpr int PR    = 36;            // words per b-row (16B-aligned rows)
constexpr int PLANE = kB * PR;       // 2304 words = 9216 B per chunk plane
constexpr int SMEM_K12 = (NCH + 1) * PLANE * 4;   // 16 planes + msg = 156672 B

__device__ float xT_g[(size_t)kL * kBC];            // 512 MB [L][B][C]
__device__ float oT_g[(size_t)kL * kBC];            // 512 MB [L][B][C]

__device__ __forceinline__ uint32_t fbits(float f) { return __float_as_uint(f); }

__device__ __forceinline__ void mma_tf32(float d[4],
                                         uint32_t a0, uint32_t a1, uint32_t a2, uint32_t a3,
                                         uint32_t b0, uint32_t b1) {
    asm volatile(
        "mma.sync.aligned.m16n8k8.row.col.f32.tf32.tf32.f32 "
        "{%0,%1,%2,%3}, {%4,%5,%6,%7}, {%8,%9}, {%0,%1,%2,%3};"
        : "+f"(d[0]), "+f"(d[1]), "+f"(d[2]), "+f"(d[3])
        : "r"(a0), "r"(a1), "r"(a2), "r"(a3), "r"(b0), "r"(b1));
}

__device__ __forceinline__ void cp16(uint32_t dst, const void* src) {
    asm volatile("cp.async.ca.shared.global [%0], [%1], 16;" :: "r"(dst), "l"(src));
}
__device__ __forceinline__ void cp_commit() {
    asm volatile("cp.async.commit_group;" ::: "memory");
}
template <int N>
__device__ __forceinline__ void cp_wait() {
    asm volatile("cp.async.wait_group %0;" :: "n"(N) : "memory");
}
// Constant-foldable dispatch (call sites have compile-time n after unrolling).
__device__ __forceinline__ void cp_wait_n(int n) {
    switch (n) {
        case 0:  cp_wait<0>();  break;  case 1:  cp_wait<1>();  break;
        case 2:  cp_wait<2>();  break;  case 3:  cp_wait<3>();  break;
        case 4:  cp_wait<4>();  break;  case 5:  cp_wait<5>();  break;
        case 6:  cp_wait<6>();  break;  case 7:  cp_wait<7>();  break;
        case 8:  cp_wait<8>();  break;  case 9:  cp_wait<9>();  break;
        case 10: cp_wait<10>(); break;  case 11: cp_wait<11>(); break;
        case 12: cp_wait<12>(); break;  case 13: cp_wait<13>(); break;
        case 14: cp_wait<14>(); break;  default: cp_wait<15>(); break;
    }
}

// ---------------- 64x64 tiled transpose (proven R6-R8 code) -----------------
__device__ __forceinline__ void transpose_body(const float* __restrict__ src,
                                               float* __restrict__ dst,
                                               int src_cols, int dst_cols) {
    __shared__ float tile[64][67];
    const int C0 = blockIdx.x * 64;
    const int R0 = blockIdx.y * 64;
    const int t = threadIdx.x;
    const int row = t >> 2, seg = t & 3;

    const float* sp = src + (size_t)(R0 + row) * src_cols + C0 + seg * 16;
    float4 a0 = ((const float4*)sp)[0];
    float4 a1 = ((const float4*)sp)[1];
    float4 a2 = ((const float4*)sp)[2];
    float4 a3 = ((const float4*)sp)[3];
    float* tr = &tile[row][seg * 16];
    tr[0]=a0.x; tr[1]=a0.y; tr[2]=a0.z; tr[3]=a0.w;
    tr[4]=a1.x; tr[5]=a1.y; tr[6]=a1.z; tr[7]=a1.w;
    tr[8]=a2.x; tr[9]=a2.y; tr[10]=a2.z; tr[11]=a2.w;
    tr[12]=a3.x; tr[13]=a3.y; tr[14]=a3.z; tr[15]=a3.w;
    __syncthreads();

    float o[16];
    #pragma unroll
    for (int k = 0; k < 16; k++) o[k] = tile[seg * 16 + k][row];
    float* dp = dst + (size_t)(C0 + row) * dst_cols + R0 + seg * 16;
    ((float4*)dp)[0] = make_float4(o[0], o[1], o[2], o[3]);
    ((float4*)dp)[1] = make_float4(o[4], o[5], o[6], o[7]);
    ((float4*)dp)[2] = make_float4(o[8], o[9], o[10], o[11]);
    ((float4*)dp)[3] = make_float4(o[12], o[13], o[14], o[15]);
}

__global__ void __launch_bounds__(256) k0_transpose(const float* __restrict__ x) {
    transpose_body(x, xT_g, kL, kBC);      // grid (kL/64, kBC/64)
}
__global__ void __launch_bounds__(256) k3_transpose(float* __restrict__ out) {
    transpose_body(oT_g, out, kBC, kL);    // grid (kBC/64, kL/64)
}

// -------- per-l chunk staging: xT[l][b][c0..c0+31] -> plane [b][c] pitch 36 --
__device__ __forceinline__ void issue_chunk(uint32_t smbase, int plane,
                                            int l, int c0, int t) {
    const int b = t >> 1, h = t & 1;
    const float* src = xT_g + ((size_t)(l * kB + b)) * kC + c0 + h * 16;
    const uint32_t dst = smbase + (uint32_t)(plane * PLANE + b * PR + h * 16) * 4u;
    #pragma unroll
    for (int i = 0; i < 4; i++) cp16(dst + 16u * i, src + 4 * i);
}

// ====================== K12: fused scores+softmax+apply =====================
__global__ void __launch_bounds__(128)
k12_fused() {
    extern __shared__ float sm[];
    float* msg = sm + NCH * PLANE;

    const int t = threadIdx.x, lane = t & 31;
    const int strip = t >> 5;              // warp = 16-row strip
    const int l = blockIdx.x;
    const int r0 = lane >> 2, q4 = lane & 3;
    const uint32_t smbase = (uint32_t)__cvta_generic_to_shared(sm);

    // Issue the whole 128KB plane as 16 cp.async groups.
    #pragma unroll
    for (int ch = 0; ch < NCH; ch++) {
        issue_chunk(smbase, ch, l, ch * CCH, t);
        cp_commit();
    }

    float acc[8][4];
    #pragma unroll
    for (int j = 0; j < 8; j++)
        #pragma unroll
        for (int i = 0; i < 4; i++) acc[j][i] = 0.0f;

    // ---------------- Pass 1: S = q q^T, progressive over arriving chunks ---
    #pragma unroll
    for (int ch = 0; ch < NCH; ch++) {
        cp_wait_n(NCH - 1 - ch);           // group ch retired (constant-folded)
        __syncthreads();                   // chunk ch visible to all warps
        const float* pl = sm + ch * PLANE;
        #pragma unroll
        for (int sk = 0; sk < 4; sk++) {
            const int ca = 8 * sk + q4;
            const float* ap = pl + (strip * 16 + r0) * PR + ca;
            const uint32_t a0 = fbits(ap[0]);
            const uint32_t a1 = fbits(ap[8 * PR]);
            const uint32_t a2 = fbits(ap[4]);
            const uint32_t a3 = fbits(ap[8 * PR + 4]);
            #pragma unroll
            for (int j = 0; j < 8; j++) {
                const float* bp = pl + (8 * j + r0) * PR + ca;
                mma_tf32(acc[j], a0, a1, a2, a3, fbits(bp[0]), fbits(bp[4]));
            }
        }
    }

    // ---------------- Softmax (warp-local rows; q4-quad reductions) ---------
    {
        const float isc = 0.044194173824159216f;   // 1/sqrt(512)
        #pragma unroll
        for (int hh = 0; hh < 2; hh++) {
            float mx = -1e30f;
            #pragma unroll
            for (int j = 0; j < 8; j++) {
                acc[j][2 * hh]     *= isc;
                acc[j][2 * hh + 1] *= isc;
                mx = fmaxf(mx, fmaxf(acc[j][2 * hh], acc[j][2 * hh + 1]));
            }
            mx = fmaxf(mx, __shfl_xor_sync(0xffffffffu, mx, 1));
            mx = fmaxf(mx, __shfl_xor_sync(0xffffffffu, mx, 2));
            float ssum = 0.0f;
            #pragma unroll
            for (int j = 0; j < 8; j++) {
                const float e0 = __expf(acc[j][2 * hh] - mx);
                const float e1 = __expf(acc[j][2 * hh + 1] - mx);
                acc[j][2 * hh] = e0; acc[j][2 * hh + 1] = e1;
                ssum += e0 + e1;
            }
            ssum += __shfl_xor_sync(0xffffffffu, ssum, 1);
            ssum += __shfl_xor_sync(0xffffffffu, ssum, 2);
            const float inv = 1.0f / ssum;
            #pragma unroll
            for (int j = 0; j < 8; j++) {
                acc[j][2 * hh] *= inv; acc[j][2 * hh + 1] *= inv;
            }
        }
    }

    // ------- Permute accumulator frags -> A frags of P, in registers --------
    {
        const int srcA = (lane & 28) | (q4 >> 1);
        const int srcB = srcA | 2;
        const bool odd = (q4 & 1) != 0;
        #pragma unroll
        for (int sk = 0; sk < 8; sk++) {
            const float v0 = __shfl_sync(0xffffffffu, acc[sk][0], srcA);
            const float v1 = __shfl_sync(0xffffffffu, acc[sk][1], srcA);
            const float v2 = __shfl_sync(0xffffffffu, acc[sk][2], srcA);
            const float v3 = __shfl_sync(0xffffffffu, acc[sk][3], srcA);
            const float w0 = __shfl_sync(0xffffffffu, acc[sk][0], srcB);
            const float w1 = __shfl_sync(0xffffffffu, acc[sk][1], srcB);
            const float w2 = __shfl_sync(0xffffffffu, acc[sk][2], srcB);
            const float w3 = __shfl_sync(0xffffffffu, acc[sk][3], srcB);
            acc[sk][0] = odd ? v1 : v0;    // P[r0][8sk+q4]
            acc[sk][1] = odd ? v3 : v2;    // P[r0+8][8sk+q4]
            acc[sk][2] = odd ? w1 : w0;    // P[r0][8sk+q4+4]
            acc[sk][3] = odd ? w3 : w2;    // P[r0+8][8sk+q4+4]
        }
    }

    // ---------------- Pass 2: outT = xT + P q (planes resident) -------------
    #pragma unroll 1
    for (int ch = 0; ch < NCH; ch++) {
        const float* pl = sm + ch * PLANE;

        // Residual preload: out = x + P q via accumulate.
        float macc[4][4];
        #pragma unroll
        for (int j2 = 0; j2 < 4; j2++) {
            const float* xp = pl + (strip * 16 + r0) * PR + 8 * j2 + 2 * q4;
            macc[j2][0] = xp[0];          macc[j2][1] = xp[1];
            macc[j2][2] = xp[8 * PR];     macc[j2][3] = xp[8 * PR + 1];
        }

        #pragma unroll
        for (int sk = 0; sk < 8; sk++) {
            #pragma unroll
            for (int j2 = 0; j2 < 4; j2++) {
                const float* bp = pl + (8 * sk + q4) * PR + 8 * j2 + r0;
                mma_tf32(macc[j2],
                         fbits(acc[sk][0]), fbits(acc[sk][1]),
                         fbits(acc[sk][2]), fbits(acc[sk][3]),
                         fbits(bp[0]), fbits(bp[4 * PR]));
            }
        }

        // msg fragments -> smem [n][c] pitch PR.
        #pragma unroll
        for (int j2 = 0; j2 < 4; j2++) {
            float* mp = msg + (strip * 16 + r0) * PR + 8 * j2 + 2 * q4;
            mp[0] = macc[j2][0];          mp[1] = macc[j2][1];
            mp[8 * PR] = macc[j2][2];     mp[8 * PR + 1] = macc[j2][3];
        }
        __syncthreads();                   // msg visible

        // Epilogue: thread writes 64B contiguous to outT.
        {
            const int b = t >> 1, h = t & 1;
            const float* mp = msg + b * PR + h * 16;
            float* op = oT_g + ((size_t)(l * kB + b)) * kC + ch * CCH + h * 16;
            #pragma unroll
            for (int i = 0; i < 4; i++)
                ((float4*)op)[i] = make_float4(mp[4 * i], mp[4 * i + 1],
                                               mp[4 * i + 2], mp[4 * i + 3]);
        }
        __syncthreads();                   // msg drained before next overwrite
    }
}

}  // namespace

extern "C" void kernel_launch(void* const* d_in, const int* in_sizes, int n_in,
                              void* d_out, int out_size) {
    (void)in_sizes; (void)n_in; (void)out_size;
    const float* x = (const float*)d_in[0];
    float* out     = (float*)d_out;

    cudaFuncSetAttribute(k12_fused,
                         cudaFuncAttributeMaxDynamicSharedMemorySize, SMEM_K12);

    dim3 g0(kL / 64, kBC / 64);
    k0_transpose<<<g0, 256>>>(x);
    k12_fused<<<kL, 128, SMEM_K12>>>();
    dim3 g3(kBC / 64, kL / 64);
    k3_transpose<<<g3, 256>>>(out);
}

// round 11
// speedup vs baseline: 2.5607x; 1.1263x over previous
#include <cuda_runtime.h>
#include <cstdint>

// AttentionalPropagation R10.
//   K0:  x[B,C,L] -> xT[L,B,C]     register 4x4-block transpose (no smem)
//   K12: per-l CTA, 256 threads in 2 warp-groups. Group g owns c-chunks
//        8g..8g+7: stages them (cp.async), accumulates its partial S, and
//        runs pass 2 on them. Partial-S add + P-fragment share go through a
//        16KB smem exchange; softmax + register P-permute stay verbatim on
//        group 0 (numerically locked since R5, rel_err 2.28e-4).
//   K3:  outT -> out[B,C,L]        register 4x4-block transpose
// R9 finding: fused K12 at 128 thr / 1 CTA/SM was barrier-latency bound;
// transposes were L1-bound (32 scalar LDS/STS per thread), not DRAM-bound.

namespace {

constexpr int kB  = 64;
constexpr int kC  = 512;
constexpr int kL  = 4096;
constexpr int kBC = kB * kC;
constexpr int CCH = 32;
constexpr int NCH = kC / CCH;        // 16
constexpr int GCH = NCH / 2;         // 8 chunks per warp-group

constexpr int PR    = 36;            // words per b-row (16B-aligned rows)
constexpr int PLANE = kB * PR;       // 2304 words = 9216 B per chunk plane
// 16 data planes + per-group msg plane (x2) + exchange (re-uses msg planes? no:
// exchange happens between passes, msg planes are free then) -> 18 planes.
constexpr int SMEM_K12 = (NCH + 2) * PLANE * 4;   // 165888 B

__device__ float xT_g[(size_t)kL * kBC];            // 512 MB [L][B][C]
__device__ float oT_g[(size_t)kL * kBC];            // 512 MB [L][B][C]

__device__ __forceinline__ uint32_t fbits(float f) { return __float_as_uint(f); }

__device__ __forceinline__ void mma_tf32(float d[4],
                                         uint32_t a0, uint32_t a1, uint32_t a2, uint32_t a3,
                                         uint32_t b0, uint32_t b1) {
    asm volatile(
        "mma.sync.aligned.m16n8k8.row.col.f32.tf32.tf32.f32 "
        "{%0,%1,%2,%3}, {%4,%5,%6,%7}, {%8,%9}, {%0,%1,%2,%3};"
        : "+f"(d[0]), "+f"(d[1]), "+f"(d[2]), "+f"(d[3])
        : "r"(a0), "r"(a1), "r"(a2), "r"(a3), "r"(b0), "r"(b1));
}

__device__ __forceinline__ void cp16(uint32_t dst, const void* src) {
    asm volatile("cp.async.ca.shared.global [%0], [%1], 16;" :: "r"(dst), "l"(src));
}
__device__ __forceinline__ void cp_commit() {
    asm volatile("cp.async.commit_group;" ::: "memory");
}
template <int N>
__device__ __forceinline__ void cp_wait() {
    asm volatile("cp.async.wait_group %0;" :: "n"(N) : "memory");
}
__device__ __forceinline__ void cp_wait_n(int n) {   // constant-folded call sites
    switch (n) {
        case 0: cp_wait<0>(); break;  case 1: cp_wait<1>(); break;
        case 2: cp_wait<2>(); break;  case 3: cp_wait<3>(); break;
        case 4: cp_wait<4>(); break;  case 5: cp_wait<5>(); break;
        case 6: cp_wait<6>(); break;  default: cp_wait<7>(); break;
    }
}
__device__ __forceinline__ void bar_group(int grp) {   // 128-thread named barrier
    asm volatile("bar.sync %0, 128;" :: "r"(grp + 1) : "memory");
}

// ------------- register 4x4-block transpose: dst[c][r] = src[r][c] ----------
__device__ __forceinline__ void transpose_reg(const float* __restrict__ src,
                                              float* __restrict__ dst,
                                              int src_cols, int dst_cols) {
    const int C0 = blockIdx.x * 64;    // src col block
    const int R0 = blockIdx.y * 64;    // src row block
    const int t  = threadIdx.x;
    const int bj = t & 15;             // block col (src)
    const int bi = t >> 4;             // block row (src)

    const float* sp = src + (size_t)(R0 + 4 * bi) * src_cols + C0 + 4 * bj;
    const float4 r0 = *(const float4*)sp;
    const float4 r1 = *(const float4*)(sp + src_cols);
    const float4 r2 = *(const float4*)(sp + 2 * (size_t)src_cols);
    const float4 r3 = *(const float4*)(sp + 3 * (size_t)src_cols);

    float* dp = dst + (size_t)(C0 + 4 * bj) * dst_cols + R0 + 4 * bi;
    *(float4*)dp                          = make_float4(r0.x, r1.x, r2.x, r3.x);
    *(float4*)(dp + dst_cols)             = make_float4(r0.y, r1.y, r2.y, r3.y);
    *(float4*)(dp + 2 * (size_t)dst_cols) = make_float4(r0.z, r1.z, r2.z, r3.z);
    *(float4*)(dp + 3 * (size_t)dst_cols) = make_float4(r0.w, r1.w, r2.w, r3.w);
}

__global__ void __launch_bounds__(256) k0_transpose(const float* __restrict__ x) {
    transpose_reg(x, xT_g, kL, kBC);       // grid (kL/64, kBC/64)
}
__global__ void __launch_bounds__(256) k3_transpose(float* __restrict__ out) {
    transpose_reg(oT_g, out, kBC, kL);     // grid (kBC/64, kL/64)
}

// -------- chunk staging: xT[l][b][c0..c0+31] -> plane [b][c] pitch 36 -------
// tg in [0,128): b = tg>>1, h = tg&1 owns 64B contiguous.
__device__ __forceinline__ void issue_chunk(uint32_t smbase, int plane,
                                            int l, int c0, int tg) {
    const int b = tg >> 1, h = tg & 1;
    const float* src = xT_g + ((size_t)(l * kB + b)) * kC + c0 + h * 16;
    const uint32_t dst = smbase + (uint32_t)(plane * PLANE + b * PR + h * 16) * 4u;
    #pragma unroll
    for (int i = 0; i < 4; i++) cp16(dst + 16u * i, src + 4 * i);
}

// ====================== K12: fused scores+softmax+apply =====================
__global__ void __launch_bounds__(256)
k12_fused() {
    extern __shared__ float sm[];
    float* xch = sm + NCH * PLANE;         // 2 planes: msg[grp] in pass 2,
                                           // S/P exchange between passes.
    const int t = threadIdx.x, lane = t & 31;
    const int w = t >> 5;
    const int strip = w & 3;               // 16-row strip of the 64x64 matrix
    const int grp   = w >> 2;              // warp-group: owns chunks 8g..8g+7
    const int tg    = t & 127;             // thread-in-group
    const int l = blockIdx.x;
    const int r0 = lane >> 2, q4 = lane & 3;
    const uint32_t smbase = (uint32_t)__cvta_generic_to_shared(sm);

    // Stage this group's 8 chunks (8 cp.async groups per thread, in order).
    #pragma unroll
    for (int i = 0; i < GCH; i++) {
        const int ch = grp * GCH + i;
        issue_chunk(smbase, ch, l, ch * CCH, tg);
        cp_commit();
    }

    float acc[8][4];
    #pragma unroll
    for (int j = 0; j < 8; j++)
        #pragma unroll
        for (int i = 0; i < 4; i++) acc[j][i] = 0.0f;

    // -------- Pass 1: partial S over this group's chunks (progressive) ------
    #pragma unroll
    for (int i = 0; i < GCH; i++) {
        cp_wait_n(GCH - 1 - i);
        bar_group(grp);                    // chunk visible within the group
        const float* pl = sm + (grp * GCH + i) * PLANE;
        #pragma unroll
        for (int sk = 0; sk < 4; sk++) {
            const int ca = 8 * sk + q4;
            const float* ap = pl + (strip * 16 + r0) * PR + ca;
            const uint32_t a0 = fbits(ap[0]);
            const uint32_t a1 = fbits(ap[8 * PR]);
            const uint32_t a2 = fbits(ap[4]);
            const uint32_t a3 = fbits(ap[8 * PR + 4]);
            #pragma unroll
            for (int j = 0; j < 8; j++) {
                const float* bp = pl + (8 * j + r0) * PR + ca;
                mma_tf32(acc[j], a0, a1, a2, a3, fbits(bp[0]), fbits(bp[4]));
            }
        }
    }

    // -------- Cross-group reduction: S = S_g0 + S_g1 (exchange via smem) ----
    __syncthreads();
    if (grp == 1) {
        float* xp = xch + tg * 33;         // pitch 33: conflict-free
        #pragma unroll
        for (int j = 0; j < 8; j++)
            #pragma unroll
            for (int i = 0; i < 4; i++) xp[j * 4 + i] = acc[j][i];
    }
    __syncthreads();

    if (grp == 0) {
        const float* xp = xch + tg * 33;
        #pragma unroll
        for (int j = 0; j < 8; j++)
            #pragma unroll
            for (int i = 0; i < 4; i++) acc[j][i] += xp[j * 4 + i];

        // ---------------- Softmax (verbatim, warp-local rows) ---------------
        const float isc = 0.044194173824159216f;   // 1/sqrt(512)
        #pragma unroll
        for (int hh = 0; hh < 2; hh++) {
            float mx = -1e30f;
            #pragma unroll
            for (int j = 0; j < 8; j++) {
                acc[j][2 * hh]     *= isc;
                acc[j][2 * hh + 1] *= isc;
                mx = fmaxf(mx, fmaxf(acc[j][2 * hh], acc[j][2 * hh + 1]));
            }
            mx = fmaxf(mx, __shfl_xor_sync(0xffffffffu, mx, 1));
            mx = fmaxf(mx, __shfl_xor_sync(0xffffffffu, mx, 2));
            float ssum = 0.0f;
            #pragma unroll
            for (int j = 0; j < 8; j++) {
                const float e0 = __expf(acc[j][2 * hh] - mx);
                const float e1 = __expf(acc[j][2 * hh + 1] - mx);
                acc[j][2 * hh] = e0; acc[j][2 * hh + 1] = e1;
                ssum += e0 + e1;
            }
            ssum += __shfl_xor_sync(0xffffffffu, ssum, 1);
            ssum += __shfl_xor_sync(0xffffffffu, ssum, 2);
            const float inv = 1.0f / ssum;
            #pragma unroll
            for (int j = 0; j < 8; j++) {
                acc[j][2 * hh] *= inv; acc[j][2 * hh + 1] *= inv;
            }
        }

        // ------ Permute accumulator frags -> A frags of P (verbatim) --------
        const int srcA = (lane & 28) | (q4 >> 1);
        const int srcB = srcA | 2;
        const bool odd = (q4 & 1) != 0;
        #pragma unroll
        for (int sk = 0; sk < 8; sk++) {
            const float v0 = __shfl_sync(0xffffffffu, acc[sk][0], srcA);
            const float v1 = __shfl_sync(0xffffffffu, acc[sk][1], srcA);
            const float v2 = __shfl_sync(0xffffffffu, acc[sk][2], srcA);
            const float v3 = __shfl_sync(0xffffffffu, acc[sk][3], srcA);
            const float w0 = __shfl_sync(0xffffffffu, acc[sk][0], srcB);
            const float w1 = __shfl_sync(0xffffffffu, acc[sk][1], srcB);
            const float w2 = __shfl_sync(0xffffffffu, acc[sk][2], srcB);
            const float w3 = __shfl_sync(0xffffffffu, acc[sk][3], srcB);
            acc[sk][0] = odd ? v1 : v0;    // P[r0][8sk+q4]
            acc[sk][1] = odd ? v3 : v2;    // P[r0+8][8sk+q4]
            acc[sk][2] = odd ? w1 : w0;    // P[r0][8sk+q4+4]
            acc[sk][3] = odd ? w3 : w2;    // P[r0+8][8sk+q4+4]
        }

        // Share P A-frags with group 1 (same tg -> identical fragment role).
        float* xp2 = xch + tg * 33;
        #pragma unroll
        for (int sk = 0; sk < 8; sk++)
            #pragma unroll
            for (int i = 0; i < 4; i++) xp2[sk * 4 + i] = acc[sk][i];
    }
    __syncthreads();
    if (grp == 1) {
        const float* xp = xch + tg * 33;
        #pragma unroll
        for (int sk = 0; sk < 8; sk++)
            #pragma unroll
            for (int i = 0; i < 4; i++) acc[sk][i] = xp[sk * 4 + i];
    }
    __syncthreads();                       // xch free -> msg planes reusable

    // -------- Pass 2: outT = xT + P q over this group's chunks --------------
    float* msg = xch + grp * PLANE;
    #pragma unroll 1
    for (int i = 0; i < GCH; i++) {
        const int ch = grp * GCH + i;
        const float* pl = sm + ch * PLANE;

        // Residual preload: out = x + P q via accumulate.
        float macc[4][4];
        #pragma unroll
        for (int j2 = 0; j2 < 4; j2++) {
            const float* xp = pl + (strip * 16 + r0) * PR + 8 * j2 + 2 * q4;
            macc[j2][0] = xp[0];          macc[j2][1] = xp[1];
            macc[j2][2] = xp[8 * PR];     macc[j2][3] = xp[8 * PR + 1];
        }

        #pragma unroll
        for (int sk = 0; sk < 8; sk++) {
            #pragma unroll
            for (int j2 = 0; j2 < 4; j2++) {
                const float* bp = pl + (8 * sk + q4) * PR + 8 * j2 + r0;
                mma_tf32(macc[j2],
                         fbits(acc[sk][0]), fbits(acc[sk][1]),
                         fbits(acc[sk][2]), fbits(acc[sk][3]),
                         fbits(bp[0]), fbits(bp[4 * PR]));
            }
        }

        // msg fragments -> group msg plane [n][c] pitch PR.
        #pragma unroll
        for (int j2 = 0; j2 < 4; j2++) {
            float* mp = msg + (strip * 16 + r0) * PR + 8 * j2 + 2 * q4;
            mp[0] = macc[j2][0];          mp[1] = macc[j2][1];
            mp[8 * PR] = macc[j2][2];     mp[8 * PR + 1] = macc[j2][3];
        }
        bar_group(grp);                    // msg visible within group

        // Epilogue: 64B contiguous per thread to outT.
        {
            const int b = tg >> 1, h = tg & 1;
            const float* mp = msg + b * PR + h * 16;
            float* op = oT_g + ((size_t)(l * kB + b)) * kC + ch * CCH + h * 16;
            #pragma unroll
            for (int k = 0; k < 4; k++)
                ((float4*)op)[k] = make_float4(mp[4 * k], mp[4 * k + 1],
                                               mp[4 * k + 2], mp[4 * k + 3]);
        }
        bar_group(grp);                    // msg drained before next overwrite
    }
}

}  // namespace

extern "C" void kernel_launch(void* const* d_in, const int* in_sizes, int n_in,
                              void* d_out, int out_size) {
    (void)in_sizes; (void)n_in; (void)out_size;
    const float* x = (const float*)d_in[0];
    float* out     = (float*)d_out;

    cudaFuncSetAttribute(k12_fused,
                         cudaFuncAttributeMaxDynamicSharedMemorySize, SMEM_K12);

    dim3 g0(kL / 64, kBC / 64);
    k0_transpose<<<g0, 256>>>(x);
    k12_fused<<<kL, 256, SMEM_K12>>>();
    dim3 g3(kBC / 64, kL / 64);
    k3_transpose<<<g3, 256>>>(out);
}